// round 13
// baseline (speedup 1.0000x reference)
#include <cuda_runtime.h>
#include <cuda_fp16.h>
#include <cstdint>

// Problem constants
#define B_   16
#define NE_  512
#define NIN_ 1024
#define H_   16
#define HD_  64
#define MROWS 8192           // B_*NE_
#define KDIM 1024
#define NDIM 1024

// ---------------- scratch (device globals; no allocations allowed) ----------
__device__ __half g_xn[(size_t)MROWS * NIN_];
__device__ __half g_q [(size_t)MROWS * NIN_];   // [B,H,NE,HD]
__device__ __half g_k [(size_t)MROWS * NIN_];
__device__ __half g_v [(size_t)MROWS * NIN_];
__device__ __half g_ao[(size_t)MROWS * NIN_];   // attention output [M,1024]
__device__ float  g_o [(size_t)MROWS * NIN_];   // WO output, pre-norm2 (f32)
__device__ __half g_wr[(size_t)4 * KDIM * NDIM];// fp16 weights (WQ,WK,WV,WO)
__device__ unsigned char g_mask8[(size_t)B_ * NE_ * NE_];
__device__ int   g_mask_kind;                   // 0=u8/bool, 1=int32, 2=float32

// ---------------- helpers ----------------------------------------------------
__device__ __forceinline__ void cp16(void* dst, const void* src)
{
    uint32_t d = (uint32_t)__cvta_generic_to_shared(dst);
    asm volatile("cp.async.cg.shared.global [%0], [%1], 16;\n" :: "r"(d), "l"(src));
}
__device__ __forceinline__ uint32_t smem_u32(const void* p)
{
    uint32_t a;
    asm("{ .reg .u64 t; cvta.to.shared.u64 t, %1; cvt.u32.u64 %0, t; }"
        : "=r"(a) : "l"(p));
    return a;
}
__device__ __forceinline__ void ldm_x4(uint32_t* r, uint32_t addr)
{
    asm volatile("ldmatrix.sync.aligned.m8n8.x4.shared.b16 {%0,%1,%2,%3}, [%4];"
                 : "=r"(r[0]), "=r"(r[1]), "=r"(r[2]), "=r"(r[3]) : "r"(addr));
}
__device__ __forceinline__ void ldm_x4t(uint32_t* r, uint32_t addr)
{
    asm volatile("ldmatrix.sync.aligned.m8n8.x4.trans.shared.b16 {%0,%1,%2,%3}, [%4];"
                 : "=r"(r[0]), "=r"(r[1]), "=r"(r[2]), "=r"(r[3]) : "r"(addr));
}
__device__ __forceinline__ void mma_f16(float* c, const uint32_t* a,
                                        uint32_t b0, uint32_t b1)
{
    asm volatile(
        "mma.sync.aligned.m16n8k16.row.col.f32.f16.f16.f32 "
        "{%0,%1,%2,%3}, {%4,%5,%6,%7}, {%8,%9}, {%0,%1,%2,%3};"
        : "+f"(c[0]), "+f"(c[1]), "+f"(c[2]), "+f"(c[3])
        : "r"(a[0]), "r"(a[1]), "r"(a[2]), "r"(a[3]), "r"(b0), "r"(b1));
}

// ---------------- mask dtype detector ---------------------------------------
__global__ void mask_detect_kernel(const unsigned char* __restrict__ m)
{
    __shared__ int c1s, c2s;
    if (threadIdx.x == 0) { c1s = 0; c2s = 0; }
    __syncthreads();
    int c1 = 0, c2 = 0;
    for (int i = threadIdx.x; i < 16384; i += 256) {
        unsigned char v = m[i];
        int r = i & 3;
        if (v && r != 0) c1++;
        if (v && r <= 1) c2++;
    }
    atomicAdd(&c1s, c1);
    atomicAdd(&c2s, c2);
    __syncthreads();
    if (threadIdx.x == 0)
        g_mask_kind = (c1s == 0) ? 1 : ((c2s == 0) ? 2 : 0);
}

// ---------------- fused prep: mask convert + weight round + norm1 ------------
__global__ void prep_kernel(const unsigned char* __restrict__ mask,
                            const float* __restrict__ w0, const float* __restrict__ w1,
                            const float* __restrict__ w2, const float* __restrict__ w3,
                            const float* __restrict__ events,
                            const float* __restrict__ alpha,
                            const float* __restrict__ bias)
{
    __shared__ float red[32];
    int blk = blockIdx.x;
    int t = threadIdx.x;

    if (blk < 4096) {
        int kind = g_mask_kind;
        size_t i = ((size_t)blk * 256 + t) * 4;
        uchar4 o;
        if (kind == 1) {
            int4 v = *(const int4*)((const int*)mask + i);
            o.x = v.x != 0; o.y = v.y != 0; o.z = v.z != 0; o.w = v.w != 0;
        } else if (kind == 2) {
            float4 v = *(const float4*)((const float*)mask + i);
            o.x = v.x != 0.f; o.y = v.y != 0.f; o.z = v.z != 0.f; o.w = v.w != 0.f;
        } else {
            uchar4 v = *(const uchar4*)(mask + i);
            o.x = v.x != 0; o.y = v.y != 0; o.z = v.z != 0; o.w = v.w != 0;
        }
        *(uchar4*)(g_mask8 + i) = o;
        return;
    }
    blk -= 4096;
    if (blk < 2048) {
        int sel = blk >> 9;
        const float* src = sel == 0 ? w0 : sel == 1 ? w1 : sel == 2 ? w2 : w3;
        size_t i = (((size_t)(blk & 511) * 256) + t) * 8;
        __half* dst = g_wr + (size_t)sel * KDIM * NDIM;
        float4 v0 = *(const float4*)(src + i);
        float4 v1 = *(const float4*)(src + i + 4);
        __half2 h[4];
        h[0] = __floats2half2_rn(v0.x, v0.y);
        h[1] = __floats2half2_rn(v0.z, v0.w);
        h[2] = __floats2half2_rn(v1.x, v1.y);
        h[3] = __floats2half2_rn(v1.z, v1.w);
        *(uint4*)(dst + i) = *(const uint4*)h;
        return;
    }
    // ---- layernorm1 ----
    int row = blk - 2048;
    const float* xr = events + (size_t)row * 1024;
    float v[4];
    float s = 0.f, ss = 0.f;
#pragma unroll
    for (int i = 0; i < 4; i++) {
        v[i] = xr[t + i * 256];
        s += v[i];
        ss += v[i] * v[i];
    }
#pragma unroll
    for (int o = 16; o; o >>= 1) {
        s  += __shfl_xor_sync(0xffffffffu, s,  o);
        ss += __shfl_xor_sync(0xffffffffu, ss, o);
    }
    int w = t >> 5, l = t & 31;
    if (l == 0) { red[w] = s; red[w + 8] = ss; }
    __syncthreads();
    if (w == 0) {
        float s2  = (l < 8) ? red[l]     : 0.f;
        float ss2 = (l < 8) ? red[l + 8] : 0.f;
#pragma unroll
        for (int o = 4; o; o >>= 1) {
            s2  += __shfl_xor_sync(0xffffffffu, s2,  o);
            ss2 += __shfl_xor_sync(0xffffffffu, ss2, o);
        }
        if (l == 0) { red[16] = s2; red[17] = ss2; }
    }
    __syncthreads();
    float mean = red[16] * (1.f / 1024.f);
    float var  = (red[17] - 1024.f * mean * mean) * (1.f / 1023.f);
    var = fmaxf(var, 0.f);
    float inv = 1.f / (sqrtf(var) + 1e-6f);
    __half* yr = g_xn + (size_t)row * 1024;
#pragma unroll
    for (int i = 0; i < 4; i++) {
        int c = t + i * 256;
        yr[c] = __float2half_rn(alpha[c] * (v[i] - mean) * inv + bias[c]);
    }
}

// ---------------- layernorm2 (f32 in g_o -> f32 out) -------------------------
__global__ void norm2_kernel(const float* __restrict__ alpha,
                             const float* __restrict__ bias,
                             float* __restrict__ yout)
{
    int row = blockIdx.x;
    const float* xr = g_o + (size_t)row * 1024;
    float* yr = yout + (size_t)row * 1024;
    int t = threadIdx.x;
    float v[4];
    float s = 0.f, ss = 0.f;
#pragma unroll
    for (int i = 0; i < 4; i++) {
        v[i] = xr[t + i * 256];
        s += v[i];
        ss += v[i] * v[i];
    }
#pragma unroll
    for (int o = 16; o; o >>= 1) {
        s  += __shfl_xor_sync(0xffffffffu, s,  o);
        ss += __shfl_xor_sync(0xffffffffu, ss, o);
    }
    __shared__ float red[32];
    int w = t >> 5, l = t & 31;
    if (l == 0) { red[w] = s; red[w + 8] = ss; }
    __syncthreads();
    if (w == 0) {
        float s2  = (l < 8) ? red[l]     : 0.f;
        float ss2 = (l < 8) ? red[l + 8] : 0.f;
#pragma unroll
        for (int o = 4; o; o >>= 1) {
            s2  += __shfl_xor_sync(0xffffffffu, s2,  o);
            ss2 += __shfl_xor_sync(0xffffffffu, ss2, o);
        }
        if (l == 0) { red[16] = s2; red[17] = ss2; }
    }
    __syncthreads();
    float mean = red[16] * (1.f / 1024.f);
    float var  = (red[17] - 1024.f * mean * mean) * (1.f / 1023.f);
    var = fmaxf(var, 0.f);
    float inv = 1.f / (sqrtf(var) + 1e-6f);
#pragma unroll
    for (int i = 0; i < 4; i++) {
        int c = t + i * 256;
        yr[c] = alpha[c] * (v[i] - mean) * inv + bias[c];
    }
}

// ---------------- fp16 tensor-core GEMM (64x32 warp tiles, 2 CTAs/SM) --------
#define GA_STRIDE 144                 // bytes per 64-half row (72 halfs)
#define GA_TILE   (128 * GA_STRIDE)   // 18432 B
#define G_STAGE   (2 * GA_TILE)       // A+B per stage
#define GEMM_SMEM (3 * G_STAGE)       // 110592 B

__global__ void __launch_bounds__(256, 2)
gemm_kernel(int qkv_mode,
            const float* __restrict__ bias0,
            const float* __restrict__ bias1,
            const float* __restrict__ bias2)
{
    extern __shared__ char sh[];
    const uint32_t shb = smem_u32(sh);

    int w_sel, colBase;
    const __half* A;
    const float* bias;
    __half* Ch = nullptr;
    float* Cf = nullptr;
    int remap;
    if (qkv_mode) {
        w_sel   = blockIdx.x >> 3;
        colBase = (blockIdx.x & 7) * 128;
        A    = g_xn;
        bias = (w_sel == 0) ? bias0 : (w_sel == 1) ? bias1 : bias2;
        Ch   = (w_sel == 0) ? g_q : (w_sel == 1) ? g_k : g_v;
        remap = 1;
    } else {
        w_sel   = 3;
        colBase = blockIdx.x * 128;
        A    = g_ao;
        bias = bias0;
        Cf   = g_o;
        remap = 0;
    }
    const __half* W = g_wr + (size_t)w_sel * KDIM * NDIM;

    const int tid = threadIdx.x;
    const int wid = tid >> 5, lane = tid & 31;
    const int wm = wid & 1, wn = wid >> 1;
    const int m0 = wm * 64, n0 = wn * 32;
    const int lr = lane >> 2, lc = lane & 3;
    const int rowBase = blockIdx.y * 128;

    const __half* Ab = A + (size_t)rowBase * KDIM;
    const __half* Wb = W + (size_t)colBase * KDIM;

    float acc[4][4][4];
#pragma unroll
    for (int i = 0; i < 4; i++)
#pragma unroll
        for (int j = 0; j < 4; j++)
#pragma unroll
            for (int q = 0; q < 4; q++) acc[i][j][q] = 0.f;

    auto loadChunk = [&](int kt) {
        char* sA = sh + (kt % 3) * G_STAGE;
        char* sB = sA + GA_TILE;
#pragma unroll
        for (int i = 0; i < 4; i++) {
            int g = tid + i * 256;
            int r = g >> 3, c = g & 7;
            cp16(sA + r * GA_STRIDE + c * 16, Ab + (size_t)r * KDIM + kt * 64 + c * 8);
        }
#pragma unroll
        for (int i = 0; i < 4; i++) {
            int g = tid + i * 256;
            int r = g >> 3, c = g & 7;
            cp16(sB + r * GA_STRIDE + c * 16, Wb + (size_t)r * KDIM + kt * 64 + c * 8);
        }
        asm volatile("cp.async.commit_group;\n");
    };

    const int NK = KDIM / 64;   // 16
    loadChunk(0);
    loadChunk(1);

    const int aRow = lane & 15, aColH = (lane >> 4) << 3;
    const int bRow = ((lane >> 4) << 3) + (lane & 7);
    const int bColH = ((lane >> 3) & 1) << 3;

    for (int kt = 0; kt < NK; kt++) {
        if (kt + 1 < NK) { asm volatile("cp.async.wait_group 1;\n"); }
        else             { asm volatile("cp.async.wait_group 0;\n"); }
        __syncthreads();
        if (kt + 2 < NK) loadChunk(kt + 2);

        const uint32_t sAb = shb + (kt % 3) * G_STAGE;
        const uint32_t sBb = sAb + GA_TILE;

#pragma unroll
        for (int k16 = 0; k16 < 4; k16++) {
            uint32_t a[4][4], b[2][4];
#pragma unroll
            for (int mi = 0; mi < 4; mi++)
                ldm_x4(a[mi], sAb + (m0 + 16 * mi + aRow) * GA_STRIDE +
                              (k16 * 16 + aColH) * 2);
#pragma unroll
            for (int ni2 = 0; ni2 < 2; ni2++)
                ldm_x4(b[ni2], sBb + (n0 + ni2 * 16 + bRow) * GA_STRIDE +
                               (k16 * 16 + bColH) * 2);
#pragma unroll
            for (int mi = 0; mi < 4; mi++)
#pragma unroll
                for (int ni = 0; ni < 4; ni++)
                    mma_f16(acc[mi][ni], a[mi],
                            b[ni >> 1][(ni & 1) * 2], b[ni >> 1][(ni & 1) * 2 + 1]);
        }
        __syncthreads();
    }

#pragma unroll
    for (int mi = 0; mi < 4; mi++) {
#pragma unroll
        for (int ni = 0; ni < 4; ni++) {
            int row0 = rowBase + m0 + 16 * mi + lr;
            int col0 = colBase + n0 + 8 * ni + 2 * lc;
            float b0 = bias[col0], b1 = bias[col0 + 1];
            float v00 = acc[mi][ni][0] + b0;
            float v01 = acc[mi][ni][1] + b1;
            float v10 = acc[mi][ni][2] + b0;
            float v11 = acc[mi][ni][3] + b1;
            if (remap) {
                int bidx = row0 >> 9, e = row0 & 511;
                int hh = col0 >> 6,  d = col0 & 63;
                size_t base0 = (((size_t)(bidx * 16 + hh) * 512) + e) * 64 + d;
                *(__half2*)&Ch[base0]               = __floats2half2_rn(v00, v01);
                *(__half2*)&Ch[base0 + (size_t)512] = __floats2half2_rn(v10, v11);
            } else {
                *(float2*)&Cf[(size_t)row0 * NDIM + col0]       = make_float2(v00, v01);
                *(float2*)&Cf[(size_t)(row0 + 8) * NDIM + col0] = make_float2(v10, v11);
            }
        }
    }
}

// ---------------- attention (fp16 TC, K-dedup, half-E EV, 4-chain EV) --------
#define A_STRIDE 144                  // bytes per 64-half row
#define OFF_Q    0                    // 32 x 144 = 4608
#define OFF_KV0  4608                 // buf0: 128 x 144 = 18432
#define KVBUF    18432
#define OFF_S    41472                // 32 x 520 f32 = 66560 (E-half overlaid)
#define SST      520
#define SROWB    (SST * 4)            // 2080 bytes per score row
#define OFF_INV  108032               // 32 f32
#define ATTN_SMEM 108160

__global__ void __launch_bounds__(256, 2)
attn_kernel(float* __restrict__ e_out)
{
    extern __shared__ char sh[];
    const uint32_t shb = smem_u32(sh);
    __half* sQ   = (__half*)(sh + OFF_Q);
    float*  sS   = (float*)(sh + OFF_S);
    float*  sInv = (float*)(sh + OFF_INV);

    const int qt = blockIdx.x, h = blockIdx.y, b = blockIdx.z;
    const int tid = threadIdx.x;
    const int lane = tid & 31, wid = tid >> 5;
    const int lr = lane >> 2, lc = lane & 3;
    const int q0 = qt * 32;

    const __half* Q  = g_q + (size_t)(b * 16 + h) * 512 * 64;
    const __half* Kp = g_k + (size_t)(b * 16 + h) * 512 * 64;
    const __half* Vp = g_v + (size_t)(b * 16 + h) * 512 * 64;

    // ---- prefetch mask rows (resolve during score MMAs) ----
    uint32_t maskw[16];
    {
        const unsigned char* mrow = g_mask8 + ((size_t)b * 512 + q0) * 512;
#pragma unroll
        for (int rr = 0; rr < 4; rr++)
#pragma unroll
            for (int i = 0; i < 4; i++)
                maskw[rr * 4 + i] = *(const uint32_t*)(
                    mrow + (size_t)(wid * 4 + rr) * 512 + 4 * lane + 128 * i);
    }

    // ---- load Q tile scaled by 1/8 (exact in fp16) ----
    {
        const __half2 sc = __half2half2(__float2half(0.125f));
        int r = tid >> 3, c8 = tid & 7;
        uint4 raw = *(const uint4*)(Q + (size_t)(q0 + r) * 64 + c8 * 8);
        __half2* hp = (__half2*)&raw;
#pragma unroll
        for (int j = 0; j < 4; j++) hp[j] = __hmul2(hp[j], sc);
        *(uint4*)((char*)sQ + r * A_STRIDE + c8 * 16) = raw;
    }

    const int aRow = lane & 15, aColH = (lane >> 4) << 3;
    const int bRow = ((lane >> 4) << 3) + (lane & 7);
    const int bColH = ((lane >> 3) & 1) << 3;

    auto loadKV = [&](const __half* src, int c) {
        char* dst = sh + OFF_KV0 + (c & 1) * KVBUF;
#pragma unroll
        for (int i = 0; i < 4; i++) {
            int g = tid + i * 256;
            int r = g >> 3, cc = g & 7;
            cp16(dst + r * A_STRIDE + cc * 16,
                 src + (size_t)(c * 128 + r) * 64 + cc * 8);
        }
        asm volatile("cp.async.commit_group;\n");
    };

    // ---- scores: S[32,512], K double-buffered, warp owns 16-col strip ----
    const int n0 = wid * 16;
    loadKV(Kp, 0);

    uint32_t qf[4][2][4];               // [k16][mi][frag]
    int qfLoaded = 0;

    for (int c = 0; c < 4; c++) {
        __syncthreads();
        if (c < 3) loadKV(Kp, c + 1);
        if (c < 3) { asm volatile("cp.async.wait_group 1;\n"); }
        else       { asm volatile("cp.async.wait_group 0;\n"); }
        __syncthreads();

        if (!qfLoaded) {
            qfLoaded = 1;
#pragma unroll
            for (int k16 = 0; k16 < 4; k16++)
#pragma unroll
                for (int mi = 0; mi < 2; mi++)
                    ldm_x4(qf[k16][mi],
                           shb + OFF_Q + (mi * 16 + aRow) * A_STRIDE +
                           (k16 * 16 + aColH) * 2);
        }

        const uint32_t kvb = shb + OFF_KV0 + (c & 1) * KVBUF;
        float acc[2][2][4] = {};
#pragma unroll
        for (int k16 = 0; k16 < 4; k16++) {
            uint32_t bf[4];
            ldm_x4(bf, kvb + (n0 + bRow) * A_STRIDE + (k16 * 16 + bColH) * 2);
#pragma unroll
            for (int mi = 0; mi < 2; mi++) {
                mma_f16(acc[mi][0], qf[k16][mi], bf[0], bf[1]);
                mma_f16(acc[mi][1], qf[k16][mi], bf[2], bf[3]);
            }
        }
        const int kb = c * 128;
#pragma unroll
        for (int mi = 0; mi < 2; mi++) {
            int row = mi * 16 + lr;
#pragma unroll
            for (int ni = 0; ni < 2; ni++) {
                int col = kb + n0 + ni * 8 + 2 * lc;
                *(float2*)&sS[row * SST + col] =
                    make_float2(acc[mi][ni][0], acc[mi][ni][1]);
                *(float2*)&sS[(row + 8) * SST + col] =
                    make_float2(acc[mi][ni][2], acc[mi][ni][3]);
            }
        }
    }

    // ---- prefetch V chunk 0 into buf0 ----
    loadKV(Vp, 0);
    __syncthreads();   // sS complete

    // ---- fused masked softmax + e write + in-place E->half ----
    const float NEGINF = __int_as_float(0xff800000);
    float* erow = e_out + (((size_t)(b * 16 + h) * 512) + q0) * 512;
#pragma unroll
    for (int rr = 0; rr < 4; rr++) {
        int r = wid * 4 + rr;
        float* srow = sS + r * SST;
        float4 f[4];
#pragma unroll
        for (int i = 0; i < 4; i++) {
            f[i] = *(const float4*)&srow[4 * lane + 128 * i];
            uint32_t mm = maskw[rr * 4 + i];
            if (mm & 0x000000FFu) f[i].x = NEGINF;
            if (mm & 0x0000FF00u) f[i].y = NEGINF;
            if (mm & 0x00FF0000u) f[i].z = NEGINF;
            if (mm & 0xFF000000u) f[i].w = NEGINF;
        }
        float mx = NEGINF;
#pragma unroll
        for (int i = 0; i < 4; i++) {
            mx = fmaxf(mx, fmaxf(fmaxf(f[i].x, f[i].y), fmaxf(f[i].z, f[i].w)));
        }
#pragma unroll
        for (int o = 16; o; o >>= 1) mx = fmaxf(mx, __shfl_xor_sync(0xffffffffu, mx, o));
        float sum = 0.f;
#pragma unroll
        for (int i = 0; i < 4; i++) {
            f[i].x = __expf(f[i].x - mx);
            f[i].y = __expf(f[i].y - mx);
            f[i].z = __expf(f[i].z - mx);
            f[i].w = __expf(f[i].w - mx);
            sum += (f[i].x + f[i].y) + (f[i].z + f[i].w);
        }
#pragma unroll
        for (int o = 16; o; o >>= 1) sum += __shfl_xor_sync(0xffffffffu, sum, o);
        float inv = 1.f / sum;
        if (lane == 0) sInv[r] = inv;
        char* ehrow = (char*)srow;      // half-E overlaid on row bytes [0,1024)
#pragma unroll
        for (int i = 0; i < 4; i++) {
            __half2 h2[2];
            h2[0] = __floats2half2_rn(f[i].x, f[i].y);
            h2[1] = __floats2half2_rn(f[i].z, f[i].w);
            *(uint2*)(ehrow + (4 * lane + 128 * i) * 2) = *(const uint2*)h2;
            float4 ev = f[i];
            ev.x *= inv; ev.y *= inv; ev.z *= inv; ev.w *= inv;
            __stcs((float4*)(erow + (size_t)r * 512 + 4 * lane + 128 * i), ev);
        }
    }
    __syncthreads();

    // ---- O^T = V^T @ E^T, V double-buffered, 4 independent MMA chains ----
    const int wd = wid & 3, wq = wid >> 2;
    const int d0 = wd * 16, qb = wq * 16;
    const uint32_t ehb = shb + OFF_S;   // half-E base, row stride SROWB
    float oaccA[2][4] = {}, oaccB[2][4] = {};
    for (int c = 0; c < 4; c++) {
        __syncthreads();
        if (c < 3) loadKV(Vp, c + 1);
        if (c < 3) { asm volatile("cp.async.wait_group 1;\n"); }
        else       { asm volatile("cp.async.wait_group 0;\n"); }
        __syncthreads();

        const uint32_t kvb = shb + OFF_KV0 + (c & 1) * KVBUF;
        const int kb = c * 128;
#pragma unroll
        for (int k16 = 0; k16 < 8; k16++) {
            uint32_t a[4], bf[4];
            ldm_x4t(a, kvb + (k16 * 16 + bRow) * A_STRIDE + (d0 + bColH) * 2);
            ldm_x4(bf, ehb + (qb + bRow) * SROWB + (kb + k16 * 16 + bColH) * 2);
            if (k16 & 1) {
                mma_f16(oaccB[0], a, bf[0], bf[1]);
                mma_f16(oaccB[1], a, bf[2], bf[3]);
            } else {
                mma_f16(oaccA[0], a, bf[0], bf[1]);
                mma_f16(oaccA[1], a, bf[2], bf[3]);
            }
        }
    }
    __syncthreads();

    // ---- normalize, stage O[q][d] as half in sQ region, write coalesced ----
    __half* sO = sQ;
#pragma unroll
    for (int ni = 0; ni < 2; ni++) {
        int q = qb + ni * 8 + 2 * lc;
        float i0 = sInv[q], i1 = sInv[q + 1];
        float v0 = oaccA[ni][0] + oaccB[ni][0];
        float v1 = oaccA[ni][1] + oaccB[ni][1];
        float v2 = oaccA[ni][2] + oaccB[ni][2];
        float v3 = oaccA[ni][3] + oaccB[ni][3];
        sO[q * 72 + d0 + lr]           = __float2half_rn(v0 * i0);
        sO[(q + 1) * 72 + d0 + lr]     = __float2half_rn(v1 * i1);
        sO[q * 72 + d0 + lr + 8]       = __float2half_rn(v2 * i0);
        sO[(q + 1) * 72 + d0 + lr + 8] = __float2half_rn(v3 * i1);
    }
    __syncthreads();
    {
        int r = tid >> 3, c = tid & 7;
        uint4 v = *(const uint4*)((const char*)sO + r * A_STRIDE + c * 16);
        *(uint4*)(g_ao + ((size_t)(b * 512 + q0 + r)) * 1024 + h * 64 + c * 8) = v;
    }
}

// ---------------- launch ------------------------------------------------------
extern "C" void kernel_launch(void* const* d_in, const int* in_sizes, int n_in,
                              void* d_out, int out_size)
{
    const float*         events = (const float*)d_in[0];
    const unsigned char* mask   = (const unsigned char*)d_in[1];
    const float*         n1a    = (const float*)d_in[2];
    const float*         n1b    = (const float*)d_in[3];
    const float*         wq     = (const float*)d_in[4];
    const float*         bq     = (const float*)d_in[5];
    const float*         wk     = (const float*)d_in[6];
    const float*         bk     = (const float*)d_in[7];
    const float*         wv     = (const float*)d_in[8];
    const float*         bv     = (const float*)d_in[9];
    const float*         wo     = (const float*)d_in[10];
    const float*         bo     = (const float*)d_in[11];
    const float*         n2a    = (const float*)d_in[12];
    const float*         n2b    = (const float*)d_in[13];

    float* out   = (float*)d_out;                       // [16,512,1024]
    float* e_out = out + (size_t)MROWS * 1024;          // [16,16,512,512]

    mask_detect_kernel<<<1, 256>>>(mask);
    prep_kernel<<<4096 + 2048 + MROWS, 256>>>(mask, wq, wk, wv, wo,
                                              events, n1a, n1b);

    cudaFuncSetAttribute(gemm_kernel,
                         cudaFuncAttributeMaxDynamicSharedMemorySize, GEMM_SMEM);
    gemm_kernel<<<dim3(24, MROWS / 128), 256, GEMM_SMEM>>>(1, bq, bk, bv);

    cudaFuncSetAttribute(attn_kernel,
                         cudaFuncAttributeMaxDynamicSharedMemorySize, ATTN_SMEM);
    attn_kernel<<<dim3(16, 16, 16), 256, ATTN_SMEM>>>(e_out);

    gemm_kernel<<<dim3(8, MROWS / 128), 256, GEMM_SMEM>>>(0, bo, nullptr, nullptr);

    norm2_kernel<<<MROWS, 256>>>(n2a, n2b, out);
}

// round 14
// speedup vs baseline: 1.0491x; 1.0491x over previous
#include <cuda_runtime.h>
#include <cuda_fp16.h>
#include <cstdint>

// Problem constants
#define B_   16
#define NE_  512
#define NIN_ 1024
#define H_   16
#define HD_  64
#define MROWS 8192           // B_*NE_
#define KDIM 1024
#define NDIM 1024

// ---------------- scratch (device globals; no allocations allowed) ----------
__device__ __half g_xn[(size_t)MROWS * NIN_];
__device__ __half g_q [(size_t)MROWS * NIN_];   // [B,H,NE,HD]
__device__ __half g_k [(size_t)MROWS * NIN_];
__device__ __half g_v [(size_t)MROWS * NIN_];
__device__ __half g_ao[(size_t)MROWS * NIN_];   // attention output [M,1024]
__device__ float  g_o [(size_t)MROWS * NIN_];   // WO output, pre-norm2 (f32)
__device__ __half g_wr[(size_t)4 * KDIM * NDIM];// fp16 weights (WQ,WK,WV,WO)
__device__ unsigned char g_mask8[(size_t)B_ * NE_ * NE_];
__device__ int   g_mask_kind;                   // 0=u8/bool, 1=int32, 2=float32

// ---------------- helpers ----------------------------------------------------
__device__ __forceinline__ void cp16(void* dst, const void* src)
{
    uint32_t d = (uint32_t)__cvta_generic_to_shared(dst);
    asm volatile("cp.async.cg.shared.global [%0], [%1], 16;\n" :: "r"(d), "l"(src));
}
__device__ __forceinline__ uint32_t smem_u32(const void* p)
{
    uint32_t a;
    asm("{ .reg .u64 t; cvta.to.shared.u64 t, %1; cvt.u32.u64 %0, t; }"
        : "=r"(a) : "l"(p));
    return a;
}
__device__ __forceinline__ void ldm_x4(uint32_t* r, uint32_t addr)
{
    asm volatile("ldmatrix.sync.aligned.m8n8.x4.shared.b16 {%0,%1,%2,%3}, [%4];"
                 : "=r"(r[0]), "=r"(r[1]), "=r"(r[2]), "=r"(r[3]) : "r"(addr));
}
__device__ __forceinline__ void ldm_x4t(uint32_t* r, uint32_t addr)
{
    asm volatile("ldmatrix.sync.aligned.m8n8.x4.trans.shared.b16 {%0,%1,%2,%3}, [%4];"
                 : "=r"(r[0]), "=r"(r[1]), "=r"(r[2]), "=r"(r[3]) : "r"(addr));
}
__device__ __forceinline__ void mma_f16(float* c, const uint32_t* a,
                                        uint32_t b0, uint32_t b1)
{
    asm volatile(
        "mma.sync.aligned.m16n8k16.row.col.f32.f16.f16.f32 "
        "{%0,%1,%2,%3}, {%4,%5,%6,%7}, {%8,%9}, {%0,%1,%2,%3};"
        : "+f"(c[0]), "+f"(c[1]), "+f"(c[2]), "+f"(c[3])
        : "r"(a[0]), "r"(a[1]), "r"(a[2]), "r"(a[3]), "r"(b0), "r"(b1));
}

// ---------------- mask dtype detector ---------------------------------------
__global__ void mask_detect_kernel(const unsigned char* __restrict__ m)
{
    __shared__ int c1s, c2s;
    if (threadIdx.x == 0) { c1s = 0; c2s = 0; }
    __syncthreads();
    int c1 = 0, c2 = 0;
    for (int i = threadIdx.x; i < 16384; i += 256) {
        unsigned char v = m[i];
        int r = i & 3;
        if (v && r != 0) c1++;
        if (v && r <= 1) c2++;
    }
    atomicAdd(&c1s, c1);
    atomicAdd(&c2s, c2);
    __syncthreads();
    if (threadIdx.x == 0)
        g_mask_kind = (c1s == 0) ? 1 : ((c2s == 0) ? 2 : 0);
}

// ---------------- fused prep: mask convert + weight round + norm1 ------------
__global__ void prep_kernel(const unsigned char* __restrict__ mask,
                            const float* __restrict__ w0, const float* __restrict__ w1,
                            const float* __restrict__ w2, const float* __restrict__ w3,
                            const float* __restrict__ events,
                            const float* __restrict__ alpha,
                            const float* __restrict__ bias)
{
    __shared__ float red[32];
    int blk = blockIdx.x;
    int t = threadIdx.x;

    if (blk < 4096) {
        int kind = g_mask_kind;
        size_t i = ((size_t)blk * 256 + t) * 4;
        uchar4 o;
        if (kind == 1) {
            int4 v = *(const int4*)((const int*)mask + i);
            o.x = v.x != 0; o.y = v.y != 0; o.z = v.z != 0; o.w = v.w != 0;
        } else if (kind == 2) {
            float4 v = *(const float4*)((const float*)mask + i);
            o.x = v.x != 0.f; o.y = v.y != 0.f; o.z = v.z != 0.f; o.w = v.w != 0.f;
        } else {
            uchar4 v = *(const uchar4*)(mask + i);
            o.x = v.x != 0; o.y = v.y != 0; o.z = v.z != 0; o.w = v.w != 0;
        }
        *(uchar4*)(g_mask8 + i) = o;
        return;
    }
    blk -= 4096;
    if (blk < 2048) {
        int sel = blk >> 9;
        const float* src = sel == 0 ? w0 : sel == 1 ? w1 : sel == 2 ? w2 : w3;
        size_t i = (((size_t)(blk & 511) * 256) + t) * 8;
        __half* dst = g_wr + (size_t)sel * KDIM * NDIM;
        float4 v0 = *(const float4*)(src + i);
        float4 v1 = *(const float4*)(src + i + 4);
        __half2 h[4];
        h[0] = __floats2half2_rn(v0.x, v0.y);
        h[1] = __floats2half2_rn(v0.z, v0.w);
        h[2] = __floats2half2_rn(v1.x, v1.y);
        h[3] = __floats2half2_rn(v1.z, v1.w);
        *(uint4*)(dst + i) = *(const uint4*)h;
        return;
    }
    // ---- layernorm1 ----
    int row = blk - 2048;
    const float* xr = events + (size_t)row * 1024;
    float v[4];
    float s = 0.f, ss = 0.f;
#pragma unroll
    for (int i = 0; i < 4; i++) {
        v[i] = xr[t + i * 256];
        s += v[i];
        ss += v[i] * v[i];
    }
#pragma unroll
    for (int o = 16; o; o >>= 1) {
        s  += __shfl_xor_sync(0xffffffffu, s,  o);
        ss += __shfl_xor_sync(0xffffffffu, ss, o);
    }
    int w = t >> 5, l = t & 31;
    if (l == 0) { red[w] = s; red[w + 8] = ss; }
    __syncthreads();
    if (w == 0) {
        float s2  = (l < 8) ? red[l]     : 0.f;
        float ss2 = (l < 8) ? red[l + 8] : 0.f;
#pragma unroll
        for (int o = 4; o; o >>= 1) {
            s2  += __shfl_xor_sync(0xffffffffu, s2,  o);
            ss2 += __shfl_xor_sync(0xffffffffu, ss2, o);
        }
        if (l == 0) { red[16] = s2; red[17] = ss2; }
    }
    __syncthreads();
    float mean = red[16] * (1.f / 1024.f);
    float var  = (red[17] - 1024.f * mean * mean) * (1.f / 1023.f);
    var = fmaxf(var, 0.f);
    float inv = 1.f / (sqrtf(var) + 1e-6f);
    __half* yr = g_xn + (size_t)row * 1024;
#pragma unroll
    for (int i = 0; i < 4; i++) {
        int c = t + i * 256;
        yr[c] = __float2half_rn(alpha[c] * (v[i] - mean) * inv + bias[c]);
    }
}

// ---------------- layernorm2 (f32 in g_o -> f32 out) -------------------------
__global__ void norm2_kernel(const float* __restrict__ alpha,
                             const float* __restrict__ bias,
                             float* __restrict__ yout)
{
    int row = blockIdx.x;
    const float* xr = g_o + (size_t)row * 1024;
    float* yr = yout + (size_t)row * 1024;
    int t = threadIdx.x;
    float v[4];
    float s = 0.f, ss = 0.f;
#pragma unroll
    for (int i = 0; i < 4; i++) {
        v[i] = xr[t + i * 256];
        s += v[i];
        ss += v[i] * v[i];
    }
#pragma unroll
    for (int o = 16; o; o >>= 1) {
        s  += __shfl_xor_sync(0xffffffffu, s,  o);
        ss += __shfl_xor_sync(0xffffffffu, ss, o);
    }
    __shared__ float red[32];
    int w = t >> 5, l = t & 31;
    if (l == 0) { red[w] = s; red[w + 8] = ss; }
    __syncthreads();
    if (w == 0) {
        float s2  = (l < 8) ? red[l]     : 0.f;
        float ss2 = (l < 8) ? red[l + 8] : 0.f;
#pragma unroll
        for (int o = 4; o; o >>= 1) {
            s2  += __shfl_xor_sync(0xffffffffu, s2,  o);
            ss2 += __shfl_xor_sync(0xffffffffu, ss2, o);
        }
        if (l == 0) { red[16] = s2; red[17] = ss2; }
    }
    __syncthreads();
    float mean = red[16] * (1.f / 1024.f);
    float var  = (red[17] - 1024.f * mean * mean) * (1.f / 1023.f);
    var = fmaxf(var, 0.f);
    float inv = 1.f / (sqrtf(var) + 1e-6f);
#pragma unroll
    for (int i = 0; i < 4; i++) {
        int c = t + i * 256;
        yr[c] = alpha[c] * (v[i] - mean) * inv + bias[c];
    }
}

// ---------------- fp16 tensor-core GEMM (64x32 warp tiles, 2 CTAs/SM) --------
#define GA_STRIDE 144                 // bytes per 64-half row (72 halfs)
#define GA_TILE   (128 * GA_STRIDE)   // 18432 B
#define G_STAGE   (2 * GA_TILE)       // A+B per stage
#define GEMM_SMEM (3 * G_STAGE)       // 110592 B

__global__ void __launch_bounds__(256, 2)
gemm_kernel(int qkv_mode,
            const float* __restrict__ bias0,
            const float* __restrict__ bias1,
            const float* __restrict__ bias2)
{
    extern __shared__ char sh[];
    const uint32_t shb = smem_u32(sh);

    int w_sel, colBase;
    const __half* A;
    const float* bias;
    __half* Ch = nullptr;
    float* Cf = nullptr;
    int remap;
    if (qkv_mode) {
        w_sel   = blockIdx.x >> 3;
        colBase = (blockIdx.x & 7) * 128;
        A    = g_xn;
        bias = (w_sel == 0) ? bias0 : (w_sel == 1) ? bias1 : bias2;
        Ch   = (w_sel == 0) ? g_q : (w_sel == 1) ? g_k : g_v;
        remap = 1;
    } else {
        w_sel   = 3;
        colBase = blockIdx.x * 128;
        A    = g_ao;
        bias = bias0;
        Cf   = g_o;
        remap = 0;
    }
    const __half* W = g_wr + (size_t)w_sel * KDIM * NDIM;

    const int tid = threadIdx.x;
    const int wid = tid >> 5, lane = tid & 31;
    const int wm = wid & 1, wn = wid >> 1;
    const int m0 = wm * 64, n0 = wn * 32;
    const int lr = lane >> 2, lc = lane & 3;
    const int rowBase = blockIdx.y * 128;

    const __half* Ab = A + (size_t)rowBase * KDIM;
    const __half* Wb = W + (size_t)colBase * KDIM;

    float acc[4][4][4];
#pragma unroll
    for (int i = 0; i < 4; i++)
#pragma unroll
        for (int j = 0; j < 4; j++)
#pragma unroll
            for (int q = 0; q < 4; q++) acc[i][j][q] = 0.f;

    auto loadChunk = [&](int kt) {
        char* sA = sh + (kt % 3) * G_STAGE;
        char* sB = sA + GA_TILE;
#pragma unroll
        for (int i = 0; i < 4; i++) {
            int g = tid + i * 256;
            int r = g >> 3, c = g & 7;
            cp16(sA + r * GA_STRIDE + c * 16, Ab + (size_t)r * KDIM + kt * 64 + c * 8);
        }
#pragma unroll
        for (int i = 0; i < 4; i++) {
            int g = tid + i * 256;
            int r = g >> 3, c = g & 7;
            cp16(sB + r * GA_STRIDE + c * 16, Wb + (size_t)r * KDIM + kt * 64 + c * 8);
        }
        asm volatile("cp.async.commit_group;\n");
    };

    const int NK = KDIM / 64;   // 16
    loadChunk(0);
    loadChunk(1);

    const int aRow = lane & 15, aColH = (lane >> 4) << 3;
    const int bRow = ((lane >> 4) << 3) + (lane & 7);
    const int bColH = ((lane >> 3) & 1) << 3;

    for (int kt = 0; kt < NK; kt++) {
        if (kt + 1 < NK) { asm volatile("cp.async.wait_group 1;\n"); }
        else             { asm volatile("cp.async.wait_group 0;\n"); }
        __syncthreads();
        if (kt + 2 < NK) loadChunk(kt + 2);

        const uint32_t sAb = shb + (kt % 3) * G_STAGE;
        const uint32_t sBb = sAb + GA_TILE;

#pragma unroll
        for (int k16 = 0; k16 < 4; k16++) {
            uint32_t a[4][4], b[2][4];
#pragma unroll
            for (int mi = 0; mi < 4; mi++)
                ldm_x4(a[mi], sAb + (m0 + 16 * mi + aRow) * GA_STRIDE +
                              (k16 * 16 + aColH) * 2);
#pragma unroll
            for (int ni2 = 0; ni2 < 2; ni2++)
                ldm_x4(b[ni2], sBb + (n0 + ni2 * 16 + bRow) * GA_STRIDE +
                               (k16 * 16 + bColH) * 2);
#pragma unroll
            for (int mi = 0; mi < 4; mi++)
#pragma unroll
                for (int ni = 0; ni < 4; ni++)
                    mma_f16(acc[mi][ni], a[mi],
                            b[ni >> 1][(ni & 1) * 2], b[ni >> 1][(ni & 1) * 2 + 1]);
        }
        __syncthreads();
    }

#pragma unroll
    for (int mi = 0; mi < 4; mi++) {
#pragma unroll
        for (int ni = 0; ni < 4; ni++) {
            int row0 = rowBase + m0 + 16 * mi + lr;
            int col0 = colBase + n0 + 8 * ni + 2 * lc;
            float b0 = bias[col0], b1 = bias[col0 + 1];
            float v00 = acc[mi][ni][0] + b0;
            float v01 = acc[mi][ni][1] + b1;
            float v10 = acc[mi][ni][2] + b0;
            float v11 = acc[mi][ni][3] + b1;
            if (remap) {
                int bidx = row0 >> 9, e = row0 & 511;
                int hh = col0 >> 6,  d = col0 & 63;
                size_t base0 = (((size_t)(bidx * 16 + hh) * 512) + e) * 64 + d;
                *(__half2*)&Ch[base0]               = __floats2half2_rn(v00, v01);
                *(__half2*)&Ch[base0 + (size_t)512] = __floats2half2_rn(v10, v11);
            } else {
                *(float2*)&Cf[(size_t)row0 * NDIM + col0]       = make_float2(v00, v01);
                *(float2*)&Cf[(size_t)(row0 + 8) * NDIM + col0] = make_float2(v10, v11);
            }
        }
    }
}

// ---------------- attention (fp16 TC, K-dedup, half-E EV w/ swizzle) ---------
#define A_STRIDE 144                  // bytes per 64-half row
#define OFF_Q    0                    // 32 x 144 = 4608
#define OFF_KV0  4608                 // buf0: 128 x 144 = 18432
#define KVBUF    18432
#define OFF_S    41472                // 32 x 520 f32 = 66560 (E-half overlaid)
#define SST      520
#define SROWB    (SST * 4)            // 2080 bytes per score row
#define ESWZ(row, off) ((off) ^ (((row) & 4) << 2))   // 16B swap -> no conflicts
#define OFF_INV  108032               // 32 f32
#define ATTN_SMEM 108160

__global__ void __launch_bounds__(256, 2)
attn_kernel(float* __restrict__ e_out)
{
    extern __shared__ char sh[];
    const uint32_t shb = smem_u32(sh);
    __half* sQ   = (__half*)(sh + OFF_Q);
    float*  sS   = (float*)(sh + OFF_S);
    float*  sInv = (float*)(sh + OFF_INV);

    const int qt = blockIdx.x, h = blockIdx.y, b = blockIdx.z;
    const int tid = threadIdx.x;
    const int lane = tid & 31, wid = tid >> 5;
    const int lr = lane >> 2, lc = lane & 3;
    const int q0 = qt * 32;

    const __half* Q  = g_q + (size_t)(b * 16 + h) * 512 * 64;
    const __half* Kp = g_k + (size_t)(b * 16 + h) * 512 * 64;
    const __half* Vp = g_v + (size_t)(b * 16 + h) * 512 * 64;

    // ---- prefetch mask rows (resolve during score MMAs) ----
    uint32_t maskw[16];
    {
        const unsigned char* mrow = g_mask8 + ((size_t)b * 512 + q0) * 512;
#pragma unroll
        for (int rr = 0; rr < 4; rr++)
#pragma unroll
            for (int i = 0; i < 4; i++)
                maskw[rr * 4 + i] = *(const uint32_t*)(
                    mrow + (size_t)(wid * 4 + rr) * 512 + 4 * lane + 128 * i);
    }

    // ---- load Q tile scaled by 1/8 (exact in fp16) ----
    {
        const __half2 sc = __half2half2(__float2half(0.125f));
        int r = tid >> 3, c8 = tid & 7;
        uint4 raw = *(const uint4*)(Q + (size_t)(q0 + r) * 64 + c8 * 8);
        __half2* hp = (__half2*)&raw;
#pragma unroll
        for (int j = 0; j < 4; j++) hp[j] = __hmul2(hp[j], sc);
        *(uint4*)((char*)sQ + r * A_STRIDE + c8 * 16) = raw;
    }

    const int aRow = lane & 15, aColH = (lane >> 4) << 3;
    const int bRow = ((lane >> 4) << 3) + (lane & 7);
    const int bColH = ((lane >> 3) & 1) << 3;

    auto loadKV = [&](const __half* src, int c) {
        char* dst = sh + OFF_KV0 + (c & 1) * KVBUF;
#pragma unroll
        for (int i = 0; i < 4; i++) {
            int g = tid + i * 256;
            int r = g >> 3, cc = g & 7;
            cp16(dst + r * A_STRIDE + cc * 16,
                 src + (size_t)(c * 128 + r) * 64 + cc * 8);
        }
        asm volatile("cp.async.commit_group;\n");
    };

    // ---- scores: S[32,512], K double-buffered, warp owns 16-col strip ----
    const int n0 = wid * 16;
    loadKV(Kp, 0);

    uint32_t qf[4][2][4];               // [k16][mi][frag]
    int qfLoaded = 0;

    for (int c = 0; c < 4; c++) {
        __syncthreads();
        if (c < 3) loadKV(Kp, c + 1);
        if (c < 3) { asm volatile("cp.async.wait_group 1;\n"); }
        else       { asm volatile("cp.async.wait_group 0;\n"); }
        __syncthreads();

        if (!qfLoaded) {
            qfLoaded = 1;
#pragma unroll
            for (int k16 = 0; k16 < 4; k16++)
#pragma unroll
                for (int mi = 0; mi < 2; mi++)
                    ldm_x4(qf[k16][mi],
                           shb + OFF_Q + (mi * 16 + aRow) * A_STRIDE +
                           (k16 * 16 + aColH) * 2);
        }

        const uint32_t kvb = shb + OFF_KV0 + (c & 1) * KVBUF;
        float acc[2][2][4] = {};
#pragma unroll
        for (int k16 = 0; k16 < 4; k16++) {
            uint32_t bf[4];
            ldm_x4(bf, kvb + (n0 + bRow) * A_STRIDE + (k16 * 16 + bColH) * 2);
#pragma unroll
            for (int mi = 0; mi < 2; mi++) {
                mma_f16(acc[mi][0], qf[k16][mi], bf[0], bf[1]);
                mma_f16(acc[mi][1], qf[k16][mi], bf[2], bf[3]);
            }
        }
        const int kb = c * 128;
#pragma unroll
        for (int mi = 0; mi < 2; mi++) {
            int row = mi * 16 + lr;
#pragma unroll
            for (int ni = 0; ni < 2; ni++) {
                int col = kb + n0 + ni * 8 + 2 * lc;
                *(float2*)&sS[row * SST + col] =
                    make_float2(acc[mi][ni][0], acc[mi][ni][1]);
                *(float2*)&sS[(row + 8) * SST + col] =
                    make_float2(acc[mi][ni][2], acc[mi][ni][3]);
            }
        }
    }

    // ---- prefetch V chunk 0 into buf0 ----
    loadKV(Vp, 0);
    __syncthreads();   // sS complete

    // ---- fused masked softmax + e write + in-place E->half (swizzled) ----
    const float NEGINF = __int_as_float(0xff800000);
    float* erow = e_out + (((size_t)(b * 16 + h) * 512) + q0) * 512;
#pragma unroll
    for (int rr = 0; rr < 4; rr++) {
        int r = wid * 4 + rr;
        float* srow = sS + r * SST;
        float4 f[4];
#pragma unroll
        for (int i = 0; i < 4; i++) {
            f[i] = *(const float4*)&srow[4 * lane + 128 * i];
            uint32_t mm = maskw[rr * 4 + i];
            if (mm & 0x000000FFu) f[i].x = NEGINF;
            if (mm & 0x0000FF00u) f[i].y = NEGINF;
            if (mm & 0x00FF0000u) f[i].z = NEGINF;
            if (mm & 0xFF000000u) f[i].w = NEGINF;
        }
        float mx = NEGINF;
#pragma unroll
        for (int i = 0; i < 4; i++) {
            mx = fmaxf(mx, fmaxf(fmaxf(f[i].x, f[i].y), fmaxf(f[i].z, f[i].w)));
        }
#pragma unroll
        for (int o = 16; o; o >>= 1) mx = fmaxf(mx, __shfl_xor_sync(0xffffffffu, mx, o));
        float sum = 0.f;
#pragma unroll
        for (int i = 0; i < 4; i++) {
            f[i].x = __expf(f[i].x - mx);
            f[i].y = __expf(f[i].y - mx);
            f[i].z = __expf(f[i].z - mx);
            f[i].w = __expf(f[i].w - mx);
            sum += (f[i].x + f[i].y) + (f[i].z + f[i].w);
        }
#pragma unroll
        for (int o = 16; o; o >>= 1) sum += __shfl_xor_sync(0xffffffffu, sum, o);
        float inv = 1.f / sum;
        if (lane == 0) sInv[r] = inv;
        char* ehrow = (char*)srow;      // half-E overlaid on row bytes [0,1024)
#pragma unroll
        for (int i = 0; i < 4; i++) {
            __half2 h2[2];
            h2[0] = __floats2half2_rn(f[i].x, f[i].y);
            h2[1] = __floats2half2_rn(f[i].z, f[i].w);
            uint32_t off = (uint32_t)((4 * lane + 128 * i) * 2);
            *(uint2*)(ehrow + ESWZ(r, off)) = *(const uint2*)h2;
            float4 ev = f[i];
            ev.x *= inv; ev.y *= inv; ev.z *= inv; ev.w *= inv;
            __stcs((float4*)(erow + (size_t)r * 512 + 4 * lane + 128 * i), ev);
        }
    }
    __syncthreads();

    // ---- O^T = V^T @ E^T, V double-buffered, swizzled half-E ldmatrix ----
    const int wd = wid & 3, wq = wid >> 2;
    const int d0 = wd * 16, qb = wq * 16;
    const uint32_t ehb = shb + OFF_S;   // half-E base, row stride SROWB
    const int erow_l = qb + bRow;       // E row this lane's ldmatrix touches
    float oacc[2][4] = {};
    for (int c = 0; c < 4; c++) {
        __syncthreads();
        if (c < 3) loadKV(Vp, c + 1);
        if (c < 3) { asm volatile("cp.async.wait_group 1;\n"); }
        else       { asm volatile("cp.async.wait_group 0;\n"); }
        __syncthreads();

        const uint32_t kvb = shb + OFF_KV0 + (c & 1) * KVBUF;
        const int kb = c * 128;
#pragma unroll
        for (int k16 = 0; k16 < 8; k16++) {
            uint32_t a[4], bf[4];
            ldm_x4t(a, kvb + (k16 * 16 + bRow) * A_STRIDE + (d0 + bColH) * 2);
            uint32_t eoff = (uint32_t)((kb + k16 * 16 + bColH) * 2);
            ldm_x4(bf, ehb + erow_l * SROWB + ESWZ(erow_l, eoff));
            mma_f16(oacc[0], a, bf[0], bf[1]);
            mma_f16(oacc[1], a, bf[2], bf[3]);
        }
    }
    __syncthreads();

    // ---- normalize, stage O[q][d] as half in sQ region, write coalesced ----
    __half* sO = sQ;
#pragma unroll
    for (int ni = 0; ni < 2; ni++) {
        int q = qb + ni * 8 + 2 * lc;
        float i0 = sInv[q], i1 = sInv[q + 1];
        sO[q * 72 + d0 + lr]           = __float2half_rn(oacc[ni][0] * i0);
        sO[(q + 1) * 72 + d0 + lr]     = __float2half_rn(oacc[ni][1] * i1);
        sO[q * 72 + d0 + lr + 8]       = __float2half_rn(oacc[ni][2] * i0);
        sO[(q + 1) * 72 + d0 + lr + 8] = __float2half_rn(oacc[ni][3] * i1);
    }
    __syncthreads();
    {
        int r = tid >> 3, c = tid & 7;
        uint4 v = *(const uint4*)((const char*)sO + r * A_STRIDE + c * 16);
        *(uint4*)(g_ao + ((size_t)(b * 512 + q0 + r)) * 1024 + h * 64 + c * 8) = v;
    }
}

// ---------------- launch ------------------------------------------------------
extern "C" void kernel_launch(void* const* d_in, const int* in_sizes, int n_in,
                              void* d_out, int out_size)
{
    const float*         events = (const float*)d_in[0];
    const unsigned char* mask   = (const unsigned char*)d_in[1];
    const float*         n1a    = (const float*)d_in[2];
    const float*         n1b    = (const float*)d_in[3];
    const float*         wq     = (const float*)d_in[4];
    const float*         bq     = (const float*)d_in[5];
    const float*         wk     = (const float*)d_in[6];
    const float*         bk     = (const float*)d_in[7];
    const float*         wv     = (const float*)d_in[8];
    const float*         bv     = (const float*)d_in[9];
    const float*         wo     = (const float*)d_in[10];
    const float*         bo     = (const float*)d_in[11];
    const float*         n2a    = (const float*)d_in[12];
    const float*         n2b    = (const float*)d_in[13];

    float* out   = (float*)d_out;                       // [16,512,1024]
    float* e_out = out + (size_t)MROWS * 1024;          // [16,16,512,512]

    mask_detect_kernel<<<1, 256>>>(mask);
    prep_kernel<<<4096 + 2048 + MROWS, 256>>>(mask, wq, wk, wv, wo,
                                              events, n1a, n1b);

    cudaFuncSetAttribute(gemm_kernel,
                         cudaFuncAttributeMaxDynamicSharedMemorySize, GEMM_SMEM);
    gemm_kernel<<<dim3(24, MROWS / 128), 256, GEMM_SMEM>>>(1, bq, bk, bv);

    cudaFuncSetAttribute(attn_kernel,
                         cudaFuncAttributeMaxDynamicSharedMemorySize, ATTN_SMEM);
    attn_kernel<<<dim3(16, 16, 16), 256, ATTN_SMEM>>>(e_out);

    gemm_kernel<<<dim3(8, MROWS / 128), 256, GEMM_SMEM>>>(0, bo, nullptr, nullptr);

    norm2_kernel<<<MROWS, 256>>>(n2a, n2b, out);
}

// round 15
// speedup vs baseline: 1.0552x; 1.0058x over previous
#include <cuda_runtime.h>
#include <cuda_fp16.h>
#include <cstdint>

// Problem constants
#define B_   16
#define NE_  512
#define NIN_ 1024
#define H_   16
#define HD_  64
#define MROWS 8192           // B_*NE_
#define KDIM 1024
#define NDIM 1024

// ---------------- scratch (device globals; no allocations allowed) ----------
__device__ __half g_xn[(size_t)MROWS * NIN_];
__device__ __half g_q [(size_t)MROWS * NIN_];   // [B,H,NE,HD]
__device__ __half g_k [(size_t)MROWS * NIN_];
__device__ __half g_v [(size_t)MROWS * NIN_];
__device__ __half g_ao[(size_t)MROWS * NIN_];   // attention output [M,1024]
__device__ float  g_o [(size_t)MROWS * NIN_];   // WO output, pre-norm2 (f32)
__device__ __half g_wr[(size_t)4 * KDIM * NDIM];// fp16 weights (WQ,WK,WV,WO)
__device__ unsigned char g_mask8[(size_t)B_ * NE_ * NE_];
__device__ int   g_mask_kind;                   // 0=u8/bool, 1=int32, 2=float32

// ---------------- helpers ----------------------------------------------------
__device__ __forceinline__ void cp16(void* dst, const void* src)
{
    uint32_t d = (uint32_t)__cvta_generic_to_shared(dst);
    asm volatile("cp.async.cg.shared.global [%0], [%1], 16;\n" :: "r"(d), "l"(src));
}
__device__ __forceinline__ uint32_t smem_u32(const void* p)
{
    uint32_t a;
    asm("{ .reg .u64 t; cvta.to.shared.u64 t, %1; cvt.u32.u64 %0, t; }"
        : "=r"(a) : "l"(p));
    return a;
}
__device__ __forceinline__ void ldm_x4(uint32_t* r, uint32_t addr)
{
    asm volatile("ldmatrix.sync.aligned.m8n8.x4.shared.b16 {%0,%1,%2,%3}, [%4];"
                 : "=r"(r[0]), "=r"(r[1]), "=r"(r[2]), "=r"(r[3]) : "r"(addr));
}
__device__ __forceinline__ void ldm_x4t(uint32_t* r, uint32_t addr)
{
    asm volatile("ldmatrix.sync.aligned.m8n8.x4.trans.shared.b16 {%0,%1,%2,%3}, [%4];"
                 : "=r"(r[0]), "=r"(r[1]), "=r"(r[2]), "=r"(r[3]) : "r"(addr));
}
__device__ __forceinline__ void mma_f16(float* c, const uint32_t* a,
                                        uint32_t b0, uint32_t b1)
{
    asm volatile(
        "mma.sync.aligned.m16n8k16.row.col.f32.f16.f16.f32 "
        "{%0,%1,%2,%3}, {%4,%5,%6,%7}, {%8,%9}, {%0,%1,%2,%3};"
        : "+f"(c[0]), "+f"(c[1]), "+f"(c[2]), "+f"(c[3])
        : "r"(a[0]), "r"(a[1]), "r"(a[2]), "r"(a[3]), "r"(b0), "r"(b1));
}

// ---------------- mask dtype detector ---------------------------------------
__global__ void mask_detect_kernel(const unsigned char* __restrict__ m)
{
    __shared__ int c1s, c2s;
    if (threadIdx.x == 0) { c1s = 0; c2s = 0; }
    __syncthreads();
    int c1 = 0, c2 = 0;
    for (int i = threadIdx.x; i < 16384; i += 256) {
        unsigned char v = m[i];
        int r = i & 3;
        if (v && r != 0) c1++;
        if (v && r <= 1) c2++;
    }
    atomicAdd(&c1s, c1);
    atomicAdd(&c2s, c2);
    __syncthreads();
    if (threadIdx.x == 0)
        g_mask_kind = (c1s == 0) ? 1 : ((c2s == 0) ? 2 : 0);
}

// ---------------- fused prep: mask convert + weight round + norm1 ------------
__global__ void prep_kernel(const unsigned char* __restrict__ mask,
                            const float* __restrict__ w0, const float* __restrict__ w1,
                            const float* __restrict__ w2, const float* __restrict__ w3,
                            const float* __restrict__ events,
                            const float* __restrict__ alpha,
                            const float* __restrict__ bias)
{
    __shared__ float red[32];
    int blk = blockIdx.x;
    int t = threadIdx.x;

    if (blk < 4096) {
        int kind = g_mask_kind;
        size_t i = ((size_t)blk * 256 + t) * 4;
        uchar4 o;
        if (kind == 1) {
            int4 v = *(const int4*)((const int*)mask + i);
            o.x = v.x != 0; o.y = v.y != 0; o.z = v.z != 0; o.w = v.w != 0;
        } else if (kind == 2) {
            float4 v = *(const float4*)((const float*)mask + i);
            o.x = v.x != 0.f; o.y = v.y != 0.f; o.z = v.z != 0.f; o.w = v.w != 0.f;
        } else {
            uchar4 v = *(const uchar4*)(mask + i);
            o.x = v.x != 0; o.y = v.y != 0; o.z = v.z != 0; o.w = v.w != 0;
        }
        *(uchar4*)(g_mask8 + i) = o;
        return;
    }
    blk -= 4096;
    if (blk < 2048) {
        int sel = blk >> 9;
        const float* src = sel == 0 ? w0 : sel == 1 ? w1 : sel == 2 ? w2 : w3;
        size_t i = (((size_t)(blk & 511) * 256) + t) * 8;
        __half* dst = g_wr + (size_t)sel * KDIM * NDIM;
        float4 v0 = *(const float4*)(src + i);
        float4 v1 = *(const float4*)(src + i + 4);
        __half2 h[4];
        h[0] = __floats2half2_rn(v0.x, v0.y);
        h[1] = __floats2half2_rn(v0.z, v0.w);
        h[2] = __floats2half2_rn(v1.x, v1.y);
        h[3] = __floats2half2_rn(v1.z, v1.w);
        *(uint4*)(dst + i) = *(const uint4*)h;
        return;
    }
    // ---- layernorm1 ----
    int row = blk - 2048;
    const float* xr = events + (size_t)row * 1024;
    float v[4];
    float s = 0.f, ss = 0.f;
#pragma unroll
    for (int i = 0; i < 4; i++) {
        v[i] = xr[t + i * 256];
        s += v[i];
        ss += v[i] * v[i];
    }
#pragma unroll
    for (int o = 16; o; o >>= 1) {
        s  += __shfl_xor_sync(0xffffffffu, s,  o);
        ss += __shfl_xor_sync(0xffffffffu, ss, o);
    }
    int w = t >> 5, l = t & 31;
    if (l == 0) { red[w] = s; red[w + 8] = ss; }
    __syncthreads();
    if (w == 0) {
        float s2  = (l < 8) ? red[l]     : 0.f;
        float ss2 = (l < 8) ? red[l + 8] : 0.f;
#pragma unroll
        for (int o = 4; o; o >>= 1) {
            s2  += __shfl_xor_sync(0xffffffffu, s2,  o);
            ss2 += __shfl_xor_sync(0xffffffffu, ss2, o);
        }
        if (l == 0) { red[16] = s2; red[17] = ss2; }
    }
    __syncthreads();
    float mean = red[16] * (1.f / 1024.f);
    float var  = (red[17] - 1024.f * mean * mean) * (1.f / 1023.f);
    var = fmaxf(var, 0.f);
    float inv = 1.f / (sqrtf(var) + 1e-6f);
    __half* yr = g_xn + (size_t)row * 1024;
#pragma unroll
    for (int i = 0; i < 4; i++) {
        int c = t + i * 256;
        yr[c] = __float2half_rn(alpha[c] * (v[i] - mean) * inv + bias[c]);
    }
}

// ---------------- layernorm2 (f32 in g_o -> f32 out) -------------------------
__global__ void norm2_kernel(const float* __restrict__ alpha,
                             const float* __restrict__ bias,
                             float* __restrict__ yout)
{
    int row = blockIdx.x;
    const float* xr = g_o + (size_t)row * 1024;
    float* yr = yout + (size_t)row * 1024;
    int t = threadIdx.x;
    float v[4];
    float s = 0.f, ss = 0.f;
#pragma unroll
    for (int i = 0; i < 4; i++) {
        v[i] = xr[t + i * 256];
        s += v[i];
        ss += v[i] * v[i];
    }
#pragma unroll
    for (int o = 16; o; o >>= 1) {
        s  += __shfl_xor_sync(0xffffffffu, s,  o);
        ss += __shfl_xor_sync(0xffffffffu, ss, o);
    }
    __shared__ float red[32];
    int w = t >> 5, l = t & 31;
    if (l == 0) { red[w] = s; red[w + 8] = ss; }
    __syncthreads();
    if (w == 0) {
        float s2  = (l < 8) ? red[l]     : 0.f;
        float ss2 = (l < 8) ? red[l + 8] : 0.f;
#pragma unroll
        for (int o = 4; o; o >>= 1) {
            s2  += __shfl_xor_sync(0xffffffffu, s2,  o);
            ss2 += __shfl_xor_sync(0xffffffffu, ss2, o);
        }
        if (l == 0) { red[16] = s2; red[17] = ss2; }
    }
    __syncthreads();
    float mean = red[16] * (1.f / 1024.f);
    float var  = (red[17] - 1024.f * mean * mean) * (1.f / 1023.f);
    var = fmaxf(var, 0.f);
    float inv = 1.f / (sqrtf(var) + 1e-6f);
#pragma unroll
    for (int i = 0; i < 4; i++) {
        int c = t + i * 256;
        yr[c] = alpha[c] * (v[i] - mean) * inv + bias[c];
    }
}

// ---------------- fp16 tensor-core GEMM (64x32 warp tiles, 2 CTAs/SM) --------
#define GA_STRIDE 144                 // bytes per 64-half row (72 halfs)
#define GA_TILE   (128 * GA_STRIDE)   // 18432 B
#define G_STAGE   (2 * GA_TILE)       // A+B per stage
#define GEMM_SMEM (3 * G_STAGE)       // 110592 B

__global__ void __launch_bounds__(256, 2)
gemm_kernel(int qkv_mode,
            const float* __restrict__ bias0,
            const float* __restrict__ bias1,
            const float* __restrict__ bias2)
{
    extern __shared__ char sh[];
    const uint32_t shb = smem_u32(sh);

    int w_sel, colBase;
    const __half* A;
    const float* bias;
    __half* Ch = nullptr;
    float* Cf = nullptr;
    int remap;
    if (qkv_mode) {
        w_sel   = blockIdx.x >> 3;
        colBase = (blockIdx.x & 7) * 128;
        A    = g_xn;
        bias = (w_sel == 0) ? bias0 : (w_sel == 1) ? bias1 : bias2;
        Ch   = (w_sel == 0) ? g_q : (w_sel == 1) ? g_k : g_v;
        remap = 1;
    } else {
        w_sel   = 3;
        colBase = blockIdx.x * 128;
        A    = g_ao;
        bias = bias0;
        Cf   = g_o;
        remap = 0;
    }
    const __half* W = g_wr + (size_t)w_sel * KDIM * NDIM;

    const int tid = threadIdx.x;
    const int wid = tid >> 5, lane = tid & 31;
    const int wm = wid & 1, wn = wid >> 1;
    const int m0 = wm * 64, n0 = wn * 32;
    const int lr = lane >> 2, lc = lane & 3;
    const int rowBase = blockIdx.y * 128;

    const __half* Ab = A + (size_t)rowBase * KDIM;
    const __half* Wb = W + (size_t)colBase * KDIM;

    float acc[4][4][4];
#pragma unroll
    for (int i = 0; i < 4; i++)
#pragma unroll
        for (int j = 0; j < 4; j++)
#pragma unroll
            for (int q = 0; q < 4; q++) acc[i][j][q] = 0.f;

    auto loadChunk = [&](int kt) {
        char* sA = sh + (kt % 3) * G_STAGE;
        char* sB = sA + GA_TILE;
#pragma unroll
        for (int i = 0; i < 4; i++) {
            int g = tid + i * 256;
            int r = g >> 3, c = g & 7;
            cp16(sA + r * GA_STRIDE + c * 16, Ab + (size_t)r * KDIM + kt * 64 + c * 8);
        }
#pragma unroll
        for (int i = 0; i < 4; i++) {
            int g = tid + i * 256;
            int r = g >> 3, c = g & 7;
            cp16(sB + r * GA_STRIDE + c * 16, Wb + (size_t)r * KDIM + kt * 64 + c * 8);
        }
        asm volatile("cp.async.commit_group;\n");
    };

    const int NK = KDIM / 64;   // 16
    loadChunk(0);
    loadChunk(1);

    const int aRow = lane & 15, aColH = (lane >> 4) << 3;
    const int bRow = ((lane >> 4) << 3) + (lane & 7);
    const int bColH = ((lane >> 3) & 1) << 3;

    for (int kt = 0; kt < NK; kt++) {
        if (kt + 1 < NK) { asm volatile("cp.async.wait_group 1;\n"); }
        else             { asm volatile("cp.async.wait_group 0;\n"); }
        __syncthreads();
        if (kt + 2 < NK) loadChunk(kt + 2);

        const uint32_t sAb = shb + (kt % 3) * G_STAGE;
        const uint32_t sBb = sAb + GA_TILE;

#pragma unroll
        for (int k16 = 0; k16 < 4; k16++) {
            uint32_t a[4][4], b[2][4];
#pragma unroll
            for (int mi = 0; mi < 4; mi++)
                ldm_x4(a[mi], sAb + (m0 + 16 * mi + aRow) * GA_STRIDE +
                              (k16 * 16 + aColH) * 2);
#pragma unroll
            for (int ni2 = 0; ni2 < 2; ni2++)
                ldm_x4(b[ni2], sBb + (n0 + ni2 * 16 + bRow) * GA_STRIDE +
                               (k16 * 16 + bColH) * 2);
#pragma unroll
            for (int mi = 0; mi < 4; mi++)
#pragma unroll
                for (int ni = 0; ni < 4; ni++)
                    mma_f16(acc[mi][ni], a[mi],
                            b[ni >> 1][(ni & 1) * 2], b[ni >> 1][(ni & 1) * 2 + 1]);
        }
        __syncthreads();
    }

#pragma unroll
    for (int mi = 0; mi < 4; mi++) {
#pragma unroll
        for (int ni = 0; ni < 4; ni++) {
            int row0 = rowBase + m0 + 16 * mi + lr;
            int col0 = colBase + n0 + 8 * ni + 2 * lc;
            float b0 = bias[col0], b1 = bias[col0 + 1];
            float v00 = acc[mi][ni][0] + b0;
            float v01 = acc[mi][ni][1] + b1;
            float v10 = acc[mi][ni][2] + b0;
            float v11 = acc[mi][ni][3] + b1;
            if (remap) {
                int bidx = row0 >> 9, e = row0 & 511;
                int hh = col0 >> 6,  d = col0 & 63;
                size_t base0 = (((size_t)(bidx * 16 + hh) * 512) + e) * 64 + d;
                *(__half2*)&Ch[base0]               = __floats2half2_rn(v00, v01);
                *(__half2*)&Ch[base0 + (size_t)512] = __floats2half2_rn(v10, v11);
            } else {
                *(float2*)&Cf[(size_t)row0 * NDIM + col0]       = make_float2(v00, v01);
                *(float2*)&Cf[(size_t)(row0 + 8) * NDIM + col0] = make_float2(v10, v11);
            }
        }
    }
}

// ---------------- attention (fp16 TC, fully swizzled score/E smem) -----------
#define A_STRIDE 144                  // bytes per 64-half row
#define OFF_Q    0                    // 32 x 144 = 4608
#define OFF_KV0  4608                 // buf0: 128 x 144 = 18432
#define KVBUF    18432
#define OFF_S    41472                // 32 x 520 f32 = 66560 (E-half overlaid)
#define SST      520
#define SROWB    (SST * 4)            // 2080 bytes per score row
#define ESWZ(row, off) ((off) ^ (((row) & 4) << 2))   // 16B swap -> no conflicts
#define OFF_INV  108032               // 32 f32
#define ATTN_SMEM 108160

__global__ void __launch_bounds__(256, 2)
attn_kernel(float* __restrict__ e_out)
{
    extern __shared__ char sh[];
    const uint32_t shb = smem_u32(sh);
    __half* sQ   = (__half*)(sh + OFF_Q);
    float*  sInv = (float*)(sh + OFF_INV);
    char*   sSb  = sh + OFF_S;        // score rows, byte-addressed (swizzled)

    const int qt = blockIdx.x, h = blockIdx.y, b = blockIdx.z;
    const int tid = threadIdx.x;
    const int lane = tid & 31, wid = tid >> 5;
    const int lr = lane >> 2, lc = lane & 3;
    const int q0 = qt * 32;

    const __half* Q  = g_q + (size_t)(b * 16 + h) * 512 * 64;
    const __half* Kp = g_k + (size_t)(b * 16 + h) * 512 * 64;
    const __half* Vp = g_v + (size_t)(b * 16 + h) * 512 * 64;

    // ---- prefetch mask rows (resolve during score MMAs) ----
    uint32_t maskw[16];
    {
        const unsigned char* mrow = g_mask8 + ((size_t)b * 512 + q0) * 512;
#pragma unroll
        for (int rr = 0; rr < 4; rr++)
#pragma unroll
            for (int i = 0; i < 4; i++)
                maskw[rr * 4 + i] = *(const uint32_t*)(
                    mrow + (size_t)(wid * 4 + rr) * 512 + 4 * lane + 128 * i);
    }

    // ---- load Q tile scaled by 1/8 (exact in fp16) ----
    {
        const __half2 sc = __half2half2(__float2half(0.125f));
        int r = tid >> 3, c8 = tid & 7;
        uint4 raw = *(const uint4*)(Q + (size_t)(q0 + r) * 64 + c8 * 8);
        __half2* hp = (__half2*)&raw;
#pragma unroll
        for (int j = 0; j < 4; j++) hp[j] = __hmul2(hp[j], sc);
        *(uint4*)((char*)sQ + r * A_STRIDE + c8 * 16) = raw;
    }

    const int aRow = lane & 15, aColH = (lane >> 4) << 3;
    const int bRow = ((lane >> 4) << 3) + (lane & 7);
    const int bColH = ((lane >> 3) & 1) << 3;

    auto loadKV = [&](const __half* src, int c) {
        char* dst = sh + OFF_KV0 + (c & 1) * KVBUF;
#pragma unroll
        for (int i = 0; i < 4; i++) {
            int g = tid + i * 256;
            int r = g >> 3, cc = g & 7;
            cp16(dst + r * A_STRIDE + cc * 16,
                 src + (size_t)(c * 128 + r) * 64 + cc * 8);
        }
        asm volatile("cp.async.commit_group;\n");
    };

    // ---- scores: S[32,512], K double-buffered, warp owns 16-col strip ----
    const int n0 = wid * 16;
    loadKV(Kp, 0);

    uint32_t qf[4][2][4];               // [k16][mi][frag]
    int qfLoaded = 0;

    for (int c = 0; c < 4; c++) {
        __syncthreads();
        if (c < 3) loadKV(Kp, c + 1);
        if (c < 3) { asm volatile("cp.async.wait_group 1;\n"); }
        else       { asm volatile("cp.async.wait_group 0;\n"); }
        __syncthreads();

        if (!qfLoaded) {
            qfLoaded = 1;
#pragma unroll
            for (int k16 = 0; k16 < 4; k16++)
#pragma unroll
                for (int mi = 0; mi < 2; mi++)
                    ldm_x4(qf[k16][mi],
                           shb + OFF_Q + (mi * 16 + aRow) * A_STRIDE +
                           (k16 * 16 + aColH) * 2);
        }

        const uint32_t kvb = shb + OFF_KV0 + (c & 1) * KVBUF;
        float acc[2][2][4] = {};
#pragma unroll
        for (int k16 = 0; k16 < 4; k16++) {
            uint32_t bf[4];
            ldm_x4(bf, kvb + (n0 + bRow) * A_STRIDE + (k16 * 16 + bColH) * 2);
#pragma unroll
            for (int mi = 0; mi < 2; mi++) {
                mma_f16(acc[mi][0], qf[k16][mi], bf[0], bf[1]);
                mma_f16(acc[mi][1], qf[k16][mi], bf[2], bf[3]);
            }
        }
        const int kb = c * 128;
#pragma unroll
        for (int mi = 0; mi < 2; mi++) {
            int row = mi * 16 + lr;
#pragma unroll
            for (int ni = 0; ni < 2; ni++) {
                uint32_t bo = (uint32_t)((kb + n0 + ni * 8 + 2 * lc) * 4);
                *(float2*)(sSb + row * SROWB + ESWZ(row, bo)) =
                    make_float2(acc[mi][ni][0], acc[mi][ni][1]);
                *(float2*)(sSb + (row + 8) * SROWB + ESWZ(row + 8, bo)) =
                    make_float2(acc[mi][ni][2], acc[mi][ni][3]);
            }
        }
    }

    // ---- prefetch V chunk 0 into buf0 ----
    loadKV(Vp, 0);
    __syncthreads();   // scores complete

    // ---- fused masked softmax + e write + in-place E->half (all swizzled) ----
    const float NEGINF = __int_as_float(0xff800000);
    float* erow = e_out + (((size_t)(b * 16 + h) * 512) + q0) * 512;
#pragma unroll
    for (int rr = 0; rr < 4; rr++) {
        int r = wid * 4 + rr;
        char* srowb = sSb + r * SROWB;
        float4 f[4];
#pragma unroll
        for (int i = 0; i < 4; i++) {
            uint32_t bo = (uint32_t)((4 * lane + 128 * i) * 4);
            f[i] = *(const float4*)(srowb + ESWZ(r, bo));
            uint32_t mm = maskw[rr * 4 + i];
            if (mm & 0x000000FFu) f[i].x = NEGINF;
            if (mm & 0x0000FF00u) f[i].y = NEGINF;
            if (mm & 0x00FF0000u) f[i].z = NEGINF;
            if (mm & 0xFF000000u) f[i].w = NEGINF;
        }
        float mx = NEGINF;
#pragma unroll
        for (int i = 0; i < 4; i++) {
            mx = fmaxf(mx, fmaxf(fmaxf(f[i].x, f[i].y), fmaxf(f[i].z, f[i].w)));
        }
#pragma unroll
        for (int o = 16; o; o >>= 1) mx = fmaxf(mx, __shfl_xor_sync(0xffffffffu, mx, o));
        float sum = 0.f;
#pragma unroll
        for (int i = 0; i < 4; i++) {
            f[i].x = __expf(f[i].x - mx);
            f[i].y = __expf(f[i].y - mx);
            f[i].z = __expf(f[i].z - mx);
            f[i].w = __expf(f[i].w - mx);
            sum += (f[i].x + f[i].y) + (f[i].z + f[i].w);
        }
#pragma unroll
        for (int o = 16; o; o >>= 1) sum += __shfl_xor_sync(0xffffffffu, sum, o);
        float inv = 1.f / sum;
        if (lane == 0) sInv[r] = inv;
#pragma unroll
        for (int i = 0; i < 4; i++) {
            __half2 h2[2];
            h2[0] = __floats2half2_rn(f[i].x, f[i].y);
            h2[1] = __floats2half2_rn(f[i].z, f[i].w);
            uint32_t off = (uint32_t)((4 * lane + 128 * i) * 2);
            *(uint2*)(srowb + ESWZ(r, off)) = *(const uint2*)h2;
            float4 ev = f[i];
            ev.x *= inv; ev.y *= inv; ev.z *= inv; ev.w *= inv;
            __stcs((float4*)(erow + (size_t)r * 512 + 4 * lane + 128 * i), ev);
        }
    }
    __syncthreads();

    // ---- O^T = V^T @ E^T, V double-buffered, swizzled half-E ldmatrix ----
    const int wd = wid & 3, wq = wid >> 2;
    const int d0 = wd * 16, qb = wq * 16;
    const uint32_t ehb = shb + OFF_S;   // half-E base, row stride SROWB
    const int erow_l = qb + bRow;       // E row this lane's ldmatrix touches
    float oacc[2][4] = {};
    for (int c = 0; c < 4; c++) {
        __syncthreads();
        if (c < 3) loadKV(Vp, c + 1);
        if (c < 3) { asm volatile("cp.async.wait_group 1;\n"); }
        else       { asm volatile("cp.async.wait_group 0;\n"); }
        __syncthreads();

        const uint32_t kvb = shb + OFF_KV0 + (c & 1) * KVBUF;
        const int kb = c * 128;
#pragma unroll
        for (int k16 = 0; k16 < 8; k16++) {
            uint32_t a[4], bf[4];
            ldm_x4t(a, kvb + (k16 * 16 + bRow) * A_STRIDE + (d0 + bColH) * 2);
            uint32_t eoff = (uint32_t)((kb + k16 * 16 + bColH) * 2);
            ldm_x4(bf, ehb + erow_l * SROWB + ESWZ(erow_l, eoff));
            mma_f16(oacc[0], a, bf[0], bf[1]);
            mma_f16(oacc[1], a, bf[2], bf[3]);
        }
    }
    __syncthreads();

    // ---- normalize, stage O[q][d] as half in sQ region, write coalesced ----
    __half* sO = sQ;
#pragma unroll
    for (int ni = 0; ni < 2; ni++) {
        int q = qb + ni * 8 + 2 * lc;
        float i0 = sInv[q], i1 = sInv[q + 1];
        sO[q * 72 + d0 + lr]           = __float2half_rn(oacc[ni][0] * i0);
        sO[(q + 1) * 72 + d0 + lr]     = __float2half_rn(oacc[ni][1] * i1);
        sO[q * 72 + d0 + lr + 8]       = __float2half_rn(oacc[ni][2] * i0);
        sO[(q + 1) * 72 + d0 + lr + 8] = __float2half_rn(oacc[ni][3] * i1);
    }
    __syncthreads();
    {
        int r = tid >> 3, c = tid & 7;
        uint4 v = *(const uint4*)((const char*)sO + r * A_STRIDE + c * 16);
        *(uint4*)(g_ao + ((size_t)(b * 512 + q0 + r)) * 1024 + h * 64 + c * 8) = v;
    }
}

// ---------------- launch ------------------------------------------------------
extern "C" void kernel_launch(void* const* d_in, const int* in_sizes, int n_in,
                              void* d_out, int out_size)
{
    const float*         events = (const float*)d_in[0];
    const unsigned char* mask   = (const unsigned char*)d_in[1];
    const float*         n1a    = (const float*)d_in[2];
    const float*         n1b    = (const float*)d_in[3];
    const float*         wq     = (const float*)d_in[4];
    const float*         bq     = (const float*)d_in[5];
    const float*         wk     = (const float*)d_in[6];
    const float*         bk     = (const float*)d_in[7];
    const float*         wv     = (const float*)d_in[8];
    const float*         bv     = (const float*)d_in[9];
    const float*         wo     = (const float*)d_in[10];
    const float*         bo     = (const float*)d_in[11];
    const float*         n2a    = (const float*)d_in[12];
    const float*         n2b    = (const float*)d_in[13];

    float* out   = (float*)d_out;                       // [16,512,1024]
    float* e_out = out + (size_t)MROWS * 1024;          // [16,16,512,512]

    mask_detect_kernel<<<1, 256>>>(mask);
    prep_kernel<<<4096 + 2048 + MROWS, 256>>>(mask, wq, wk, wv, wo,
                                              events, n1a, n1b);

    cudaFuncSetAttribute(gemm_kernel,
                         cudaFuncAttributeMaxDynamicSharedMemorySize, GEMM_SMEM);
    gemm_kernel<<<dim3(24, MROWS / 128), 256, GEMM_SMEM>>>(1, bq, bk, bv);

    cudaFuncSetAttribute(attn_kernel,
                         cudaFuncAttributeMaxDynamicSharedMemorySize, ATTN_SMEM);
    attn_kernel<<<dim3(16, 16, 16), 256, ATTN_SMEM>>>(e_out);

    gemm_kernel<<<dim3(8, MROWS / 128), 256, GEMM_SMEM>>>(0, bo, nullptr, nullptr);

    norm2_kernel<<<MROWS, 256>>>(n2a, n2b, out);
}